// round 16
// baseline (speedup 1.0000x reference)
#include <cuda_runtime.h>
#include <cuda_fp16.h>
#include <cstdint>

#define BATCH 8
#define NSEQ 1024
#define DIM 768
#define NH 16
#define HD 48
#define SCALE 0.14433756729740643f  /* 48^-0.5 */
#define SPH 1032                     /* fp16 smem stride (halfs) for mix kernel */

// ---------------- scratch (static __device__, allocation-guard safe) ----------
__device__ __align__(256) __half g_xh[BATCH * NSEQ * DIM];
__device__ __align__(256) __half g_wqkvh[3 * DIM * DIM];
__device__ __align__(256) __half g_wprojh[DIM * DIM];
__device__ __align__(256) __half g_q[BATCH * NH * NSEQ * HD];       // [b][h][n][d] (pre-scaled)
__device__ __align__(256) __half g_k[BATCH * NH * NSEQ * HD];       // [b][h][n][d]
__device__ __align__(256) __half g_v[BATCH * NH * HD * NSEQ];       // [b][h][d][n]  TRANSPOSED
__device__ __align__(256) __half g_S[(size_t)BATCH * NH * NSEQ * NSEQ];
__device__ __align__(256) __half g_O[BATCH * NSEQ * DIM];           // attn out pre-proj (fp16)

// ---------------- helpers -----------------------------------------------------
__device__ __forceinline__ void mma16h(float* c, const uint32_t* a, const uint32_t* b) {
    asm volatile(
        "mma.sync.aligned.m16n8k16.row.col.f32.f16.f16.f32 "
        "{%0,%1,%2,%3},{%4,%5,%6,%7},{%8,%9},{%0,%1,%2,%3};"
        : "+f"(c[0]), "+f"(c[1]), "+f"(c[2]), "+f"(c[3])
        : "r"(a[0]), "r"(a[1]), "r"(a[2]), "r"(a[3]), "r"(b[0]), "r"(b[1]));
}
__device__ __forceinline__ void ldsm4(uint32_t& r0, uint32_t& r1, uint32_t& r2, uint32_t& r3,
                                      uint32_t addr) {
    asm volatile("ldmatrix.sync.aligned.m8n8.x4.shared.b16 {%0,%1,%2,%3}, [%4];"
        : "=r"(r0), "=r"(r1), "=r"(r2), "=r"(r3) : "r"(addr));
}
__device__ __forceinline__ void ldsm2(uint32_t& r0, uint32_t& r1, uint32_t addr) {
    asm volatile("ldmatrix.sync.aligned.m8n8.x2.shared.b16 {%0,%1}, [%2];"
        : "=r"(r0), "=r"(r1) : "r"(addr));
}
__device__ __forceinline__ void ldsm2t(uint32_t& r0, uint32_t& r1, uint32_t addr) {
    asm volatile("ldmatrix.sync.aligned.m8n8.x2.trans.shared.b16 {%0,%1}, [%2];"
        : "=r"(r0), "=r"(r1) : "r"(addr));
}
__device__ __forceinline__ uint32_t packh2(float x, float y) {
    __half2 h = __floats2half2_rn(x, y);
    return *(uint32_t*)&h;
}

#define CP16(dst_u32, src_ptr) \
    asm volatile("cp.async.cg.shared.global [%0], [%1], 16;" :: "r"(dst_u32), "l"(src_ptr))
#define CP_COMMIT()  asm volatile("cp.async.commit_group;" ::)
#define CP_WAIT(n)   asm volatile("cp.async.wait_group %0;" :: "n"(n))

// ---------------- K0: merged fp32 -> fp16 conversion (3 arrays, 1 launch) -----
__global__ __launch_bounds__(256) void f2h3_kernel(
    const float* __restrict__ a, __half* __restrict__ oa, int na4,
    const float* __restrict__ b, __half* __restrict__ ob, int nb4,
    const float* __restrict__ c, __half* __restrict__ oc, int nc4) {
    const int total = na4 + nb4 + nc4;
    for (int i = blockIdx.x * 256 + threadIdx.x; i < total; i += gridDim.x * 256) {
        const float* in;
        __half* out;
        int idx;
        if (i < na4)            { in = a; out = oa; idx = i; }
        else if (i < na4 + nb4) { in = b; out = ob; idx = i - na4; }
        else                    { in = c; out = oc; idx = i - na4 - nb4; }
        float4 v = ((const float4*)in)[idx];
        ((__half2*)out)[2 * idx]     = __floats2half2_rn(v.x, v.y);
        ((__half2*)out)[2 * idx + 1] = __floats2half2_rn(v.z, v.w);
    }
}

// ---------------- mm_fp16: qkv (MODE 0) & proj (MODE 1) -----------------------
// 512 threads, block tile 256(M) x 128(N), K-tile 32, 2-stage cp.async, fp32 acc.
#define ABUF (256 * 40 * 2)
#define WBUF (128 * 40 * 2)
template <int MODE>
__global__ __launch_bounds__(512) void mm_fp16(
    const __half* __restrict__ A, const __half* __restrict__ W,
    const float* __restrict__ bias, float* __restrict__ C, int K, int Nc) {
    extern __shared__ __half smem_mm[];

    const int tid = threadIdx.x;
    const int m0 = blockIdx.y * 256;
    const int n0 = blockIdx.x * 128;

    const int warp = tid >> 5, lane = tid & 31;
    const int wm = warp >> 2, wn = warp & 3;   // 4 x 4 warps
    const int g = lane >> 2, t = lane & 3;

    const uint32_t sa = (uint32_t)__cvta_generic_to_shared(smem_mm);
    const uint32_t sw = sa + 2 * ABUF;

    const uint32_t a_off = (uint32_t)((lane & 15) * 40 + (lane >> 4) * 8) * 2;
    const uint32_t b_off = (uint32_t)((((lane >> 4) << 3) + (lane & 7)) * 40 +
                                      (((lane >> 3) & 1) << 3)) * 2;

#define MM_CP(buf, kt)                                                         \
    do {                                                                       \
        _Pragma("unroll")                                                      \
        for (int j = 0; j < 2; j++) {         /* A: 256 rows x 4 chunks */     \
            const int i = tid + 512 * j;                                       \
            const int r = i >> 2, c = (i & 3) * 8;                             \
            CP16(sa + (buf) * ABUF + (uint32_t)(r * 40 + c) * 2,               \
                 A + (size_t)(m0 + r) * K + (kt) + c);                         \
        }                                                                      \
        {                                      /* W: 128 rows x 4 chunks */    \
            const int r = tid >> 2, c = (tid & 3) * 8;                         \
            CP16(sw + (buf) * WBUF + (uint32_t)(r * 40 + c) * 2,               \
                 W + (size_t)(n0 + r) * K + (kt) + c);                         \
        }                                                                      \
        CP_COMMIT();                                                           \
    } while (0)

    float acc[4][4][4];
#pragma unroll
    for (int i = 0; i < 4; i++)
#pragma unroll
        for (int j = 0; j < 4; j++)
#pragma unroll
            for (int e = 0; e < 4; e++) acc[i][j][e] = 0.f;

    MM_CP(0, 0);
    CP_WAIT(0);
    __syncthreads();

    int buf = 0;
    for (int kt = 32;; kt += 32) {
        const bool more = kt < K;
        if (more) MM_CP(buf ^ 1, kt);
#pragma unroll
        for (int ks = 0; ks < 2; ks++) {
            const uint32_t kb = (uint32_t)(ks * 16) * 2;
            uint32_t af[4][4], bf[4][2];
#pragma unroll
            for (int mt = 0; mt < 4; mt++)
                ldsm4(af[mt][0], af[mt][1], af[mt][2], af[mt][3],
                      sa + buf * ABUF + (uint32_t)((wm * 64 + mt * 16) * 40) * 2 + kb + a_off);
#pragma unroll
            for (int ntp = 0; ntp < 2; ntp++)
                ldsm4(bf[2 * ntp][0], bf[2 * ntp][1], bf[2 * ntp + 1][0], bf[2 * ntp + 1][1],
                      sw + buf * WBUF + (uint32_t)((wn * 32 + ntp * 16) * 40) * 2 + kb + b_off);
#pragma unroll
            for (int mt = 0; mt < 4; mt++)
#pragma unroll
                for (int nt = 0; nt < 4; nt++) mma16h(acc[mt][nt], af[mt], bf[nt]);
        }
        if (!more) break;
        CP_WAIT(0);
        __syncthreads();
        buf ^= 1;
    }

#pragma unroll
    for (int mt = 0; mt < 4; mt++) {
#pragma unroll
        for (int nt = 0; nt < 4; nt++) {
#pragma unroll
            for (int half = 0; half < 2; half++) {
                const int m = m0 + wm * 64 + mt * 16 + g + half * 8;
                const int c = n0 + wn * 32 + nt * 8 + 2 * t;   // always even
                const float v0 = acc[mt][nt][half * 2 + 0];
                const float v1 = acc[mt][nt][half * 2 + 1];
                if (MODE == 0) {
                    const float w0 = v0 + bias[c], w1 = v1 + bias[c + 1];
                    const int b = m >> 10, n = m & 1023;
                    const int ttt = c / DIM;
                    const int rr = c - ttt * DIM;
                    const int h = rr / HD, d = rr - h * HD;    // d even, d+1 same head
                    const int bh = b * NH + h;
                    if (ttt == 0)
                        *(__half2*)&g_q[((size_t)bh * NSEQ + n) * HD + d] =
                            __floats2half2_rn(w0 * SCALE, w1 * SCALE);
                    else if (ttt == 1)
                        *(__half2*)&g_k[((size_t)bh * NSEQ + n) * HD + d] =
                            __floats2half2_rn(w0, w1);
                    else {
                        g_v[((size_t)bh * HD + d) * NSEQ + n] = __float2half(w0);
                        g_v[((size_t)bh * HD + d + 1) * NSEQ + n] = __float2half(w1);
                    }
                } else {
                    float2 o = make_float2(v0 + bias[c], v1 + bias[c + 1]);
                    *(float2*)(C + (size_t)m * Nc + c) = o;
                }
            }
        }
    }
#undef MM_CP
}

// ---------------- K2: S = q @ k^T, per-batch slice; tile 128q x 256k ----------
__global__ __launch_bounds__(512) void qk_fp16(int bb) {
    __shared__ __half Qs[128][56];
    __shared__ __half Ks[256][56];

    const int tid = threadIdx.x;
    const int bh = bb * NH + blockIdx.z;
    const int q0 = blockIdx.y * 128;
    const int k0 = blockIdx.x * 256;

    const __half* Qg = g_q + (size_t)bh * NSEQ * HD;
    const __half* Kg = g_k + (size_t)bh * NSEQ * HD;

    const uint32_t sq = (uint32_t)__cvta_generic_to_shared(&Qs[0][0]);
    const uint32_t sk = (uint32_t)__cvta_generic_to_shared(&Ks[0][0]);

#pragma unroll
    for (int j = 0; j < 2; j++) {
        const int i = tid + 512 * j;
        if (i < 768) {
            const int r = i / 6, c = (i % 6) * 8;
            CP16(sq + (uint32_t)(r * 56 + c) * 2, Qg + (size_t)(q0 + r) * HD + c);
        }
    }
#pragma unroll
    for (int j = 0; j < 3; j++) {
        const int i = tid + 512 * j;
        const int r = i / 6, c = (i % 6) * 8;
        CP16(sk + (uint32_t)(r * 56 + c) * 2, Kg + (size_t)(k0 + r) * HD + c);
    }
    CP_COMMIT();
    CP_WAIT(0);
    __syncthreads();

    const int warp = tid >> 5, lane = tid & 31;
    const int wm = warp >> 3, wn = warp & 7;   // 2 x 8 warps
    const int g = lane >> 2, t = lane & 3;

    const uint32_t a_off = (uint32_t)((lane & 15) * 56 + (lane >> 4) * 8) * 2;
    const uint32_t b_off = (uint32_t)((((lane >> 4) << 3) + (lane & 7)) * 56 +
                                      (((lane >> 3) & 1) << 3)) * 2;

    float acc[4][4][4];
#pragma unroll
    for (int i = 0; i < 4; i++)
#pragma unroll
        for (int j = 0; j < 4; j++)
#pragma unroll
            for (int e = 0; e < 4; e++) acc[i][j][e] = 0.f;

#pragma unroll
    for (int ks = 0; ks < 3; ks++) {
        const uint32_t kb = (uint32_t)(ks * 16) * 2;
        uint32_t af[4][4], bf[4][2];
#pragma unroll
        for (int mt = 0; mt < 4; mt++)
            ldsm4(af[mt][0], af[mt][1], af[mt][2], af[mt][3],
                  sq + (uint32_t)((wm * 64 + mt * 16) * 56) * 2 + kb + a_off);
#pragma unroll
        for (int ntp = 0; ntp < 2; ntp++)
            ldsm4(bf[2 * ntp][0], bf[2 * ntp][1], bf[2 * ntp + 1][0], bf[2 * ntp + 1][1],
                  sk + (uint32_t)((wn * 32 + ntp * 16) * 56) * 2 + kb + b_off);
#pragma unroll
        for (int mt = 0; mt < 4; mt++)
#pragma unroll
            for (int nt = 0; nt < 4; nt++) mma16h(acc[mt][nt], af[mt], bf[nt]);
    }

    __half* Sg = g_S + (size_t)bh * NSEQ * NSEQ;
#pragma unroll
    for (int mt = 0; mt < 4; mt++)
#pragma unroll
        for (int nt = 0; nt < 4; nt++)
#pragma unroll
            for (int half = 0; half < 2; half++) {
                const int m = q0 + wm * 64 + mt * 16 + g + half * 8;
                const int c = k0 + wn * 32 + nt * 8 + 2 * t;
                *(__half2*)(Sg + (size_t)m * NSEQ + c) =
                    __floats2half2_rn(acc[mt][nt][half * 2], acc[mt][nt][half * 2 + 1]);
            }
}

// ---------------- K3: mix1 -> 1-pass softmax -> inv-folded mix2, per-batch ----
__global__ __launch_bounds__(256) void mix_softmax_kernel(
    const float* __restrict__ wl, const float* __restrict__ bl,
    const float* __restrict__ ww, const float* __restrict__ bw, int bb) {
    __shared__ __half s[NH][SPH];
    __shared__ float s_inv[NH];

    const int tid = threadIdx.x;
    const int lane = tid & 31, warp = tid >> 5;
    const int ar = lane >> 2;
    const int ac = lane & 3;
    const int q = blockIdx.x;

    const uint32_t ss = (uint32_t)__cvta_generic_to_shared(&s[0][0]);

    uint32_t la[4];
    la[0] = packh2(wl[ar * NH + 2 * ac], wl[ar * NH + 2 * ac + 1]);
    la[1] = packh2(wl[(ar + 8) * NH + 2 * ac], wl[(ar + 8) * NH + 2 * ac + 1]);
    la[2] = packh2(wl[ar * NH + 2 * ac + 8], wl[ar * NH + 2 * ac + 9]);
    la[3] = packh2(wl[(ar + 8) * NH + 2 * ac + 8], wl[(ar + 8) * NH + 2 * ac + 9]);
    float wwv[8];
    wwv[0] = ww[ar * NH + 2 * ac];        wwv[1] = ww[ar * NH + 2 * ac + 1];
    wwv[2] = ww[(ar + 8) * NH + 2 * ac];  wwv[3] = ww[(ar + 8) * NH + 2 * ac + 1];
    wwv[4] = ww[ar * NH + 2 * ac + 8];    wwv[5] = ww[ar * NH + 2 * ac + 9];
    wwv[6] = ww[(ar + 8) * NH + 2 * ac + 8]; wwv[7] = ww[(ar + 8) * NH + 2 * ac + 9];
    const float bl0 = bl[ar], bl1 = bl[ar + 8];
    const float bw0 = bw[ar], bw1 = bw[ar + 8];

    const size_t rowbase = (size_t)(bb * NH) * NSEQ * NSEQ + (size_t)q * NSEQ;

#pragma unroll
    for (int j = 0; j < 8; j++) {
        const int i = tid + 256 * j;
        const int h = i >> 7, c = (i & 127) * 8;
        CP16(ss + (uint32_t)(h * SPH + c) * 2,
             g_S + rowbase + (size_t)h * NSEQ * NSEQ + c);
    }
    CP_COMMIT();
    CP_WAIT(0);
    __syncthreads();

    const uint32_t bt_off = (uint32_t)((lane & 15) * SPH) * 2;

    // mix1 (in place; warp owns cols [warp*128, +128))
#pragma unroll 4
    for (int c0 = warp * 128; c0 < warp * 128 + 128; c0 += 8) {
        uint32_t bf[2];
        ldsm2t(bf[0], bf[1], ss + bt_off + (uint32_t)c0 * 2);
        float c[4] = {bl0, bl0, bl1, bl1};
        mma16h(c, la, bf);
        *(__half2*)&s[ar][c0 + 2 * ac] = __floats2half2_rn(c[0], c[1]);
        *(__half2*)&s[ar + 8][c0 + 2 * ac] = __floats2half2_rn(c[2], c[3]);
    }
    __syncthreads();

    // exp + sum in ONE pass (no max subtraction)
    for (int gg = warp; gg < NH; gg += 8) {
        __half2* row = (__half2*)&s[gg][0];
        float sum = 0.f;
        for (int k = lane; k < 512; k += 32) {
            float2 f = __half22float2(row[k]);
            float e0 = __expf(f.x), e1 = __expf(f.y);
            row[k] = __floats2half2_rn(e0, e1);
            sum += e0 + e1;
        }
#pragma unroll
        for (int off = 16; off > 0; off >>= 1) sum += __shfl_xor_sync(0xffffffffu, sum, off);
        if (lane == 0) s_inv[gg] = 1.f / sum;
    }
    __syncthreads();

    // fold 1/Z into mix2 A fragments
    const float i0 = s_inv[2 * ac], i1 = s_inv[2 * ac + 1];
    const float i2 = s_inv[2 * ac + 8], i3 = s_inv[2 * ac + 9];
    uint32_t wa[4];
    wa[0] = packh2(wwv[0] * i0, wwv[1] * i1);
    wa[1] = packh2(wwv[2] * i0, wwv[3] * i1);
    wa[2] = packh2(wwv[4] * i2, wwv[5] * i3);
    wa[3] = packh2(wwv[6] * i2, wwv[7] * i3);

    // mix2 in place
#pragma unroll 4
    for (int c0 = warp * 128; c0 < warp * 128 + 128; c0 += 8) {
        uint32_t bf[2];
        ldsm2t(bf[0], bf[1], ss + bt_off + (uint32_t)c0 * 2);
        float c[4] = {bw0, bw0, bw1, bw1};
        mma16h(c, wa, bf);
        *(__half2*)&s[ar][c0 + 2 * ac] = __floats2half2_rn(c[0], c[1]);
        *(__half2*)&s[ar + 8][c0 + 2 * ac] = __floats2half2_rn(c[2], c[3]);
    }
    __syncthreads();

    // coalesced store s -> g_S
#pragma unroll
    for (int j = 0; j < 8; j++) {
        const int i = tid + 256 * j;
        const int h = i >> 7, c = (i & 127) * 8;
        float4 v = *(const float4*)&s[h][c];
        *(float4*)(g_S + rowbase + (size_t)h * NSEQ * NSEQ + c) = v;
    }
}

// ---------------- K4: O = P @ V, per-batch; 64-q tile (256 blocks/batch) ------
// 256 threads, 8 warps (4 wm x 2 wn), warp tile 16q x 24d.
__global__ __launch_bounds__(256) void pv_fp16(int bb) {
    __shared__ __half Ps[2][64][40];
    __shared__ __half Vs[2][HD][40];

    const int h = blockIdx.z;
    const int bh = bb * NH + h;
    const int tid = threadIdx.x;
    const int qbase = blockIdx.x * 64;
    const __half* Pg = g_S + (size_t)bh * NSEQ * NSEQ + (size_t)qbase * NSEQ;
    const __half* Vg = g_v + (size_t)bh * HD * NSEQ;   // [d][n]

    const int warp = tid >> 5, lane = tid & 31;
    const int wm = warp >> 1, wn = warp & 1;   // 4 x 2
    const int g = lane >> 2, t = lane & 3;

    const uint32_t psa = (uint32_t)__cvta_generic_to_shared(&Ps[0][0][0]);
    const uint32_t vsa = (uint32_t)__cvta_generic_to_shared(&Vs[0][0][0]);
    const uint32_t PSZ = 64 * 40 * 2;
    const uint32_t VSZ = HD * 40 * 2;

    const uint32_t a_off = (uint32_t)((lane & 15) * 40 + (lane >> 4) * 8) * 2;
    const uint32_t b_off = (uint32_t)((((lane >> 4) << 3) + (lane & 7)) * 40 +
                                      (((lane >> 3) & 1) << 3)) * 2;
    const uint32_t b2_off = (uint32_t)((lane & 7) * 40 + (((lane >> 3) & 1) << 3)) * 2;

#define PV_CP(buf, kt)                                                          \
    do {                                                                        \
        {   /* P tile: 64 rows x 32 cols = 256 chunks of 8 halfs */             \
            const int r = tid >> 2, c = (tid & 3) * 8;                          \
            CP16(psa + (buf) * PSZ + (uint32_t)(r * 40 + c) * 2,                \
                 Pg + (size_t)r * NSEQ + (kt) + c);                             \
        }                                                                       \
        if (tid < 192) {    /* V tile: 48 rows x 32 cols */                     \
            const int d = tid >> 2, c = (tid & 3) * 8;                          \
            CP16(vsa + (buf) * VSZ + (uint32_t)(d * 40 + c) * 2,                \
                 Vg + (size_t)d * NSEQ + (kt) + c);                             \
        }                                                                       \
        CP_COMMIT();                                                            \
    } while (0)

    float acc[3][4];
#pragma unroll
    for (int j = 0; j < 3; j++)
#pragma unroll
        for (int e = 0; e < 4; e++) acc[j][e] = 0.f;

    PV_CP(0, 0);
    CP_WAIT(0);
    __syncthreads();

    int buf = 0;
    for (int kt = 32;; kt += 32) {
        const bool more = kt < NSEQ;
        if (more) PV_CP(buf ^ 1, kt);
#pragma unroll
        for (int ks = 0; ks < 2; ks++) {
            const uint32_t kb = (uint32_t)(ks * 16) * 2;
            uint32_t af[4], bf[3][2];
            ldsm4(af[0], af[1], af[2], af[3],
                  psa + buf * PSZ + (uint32_t)((wm * 16) * 40) * 2 + kb + a_off);
            ldsm4(bf[0][0], bf[0][1], bf[1][0], bf[1][1],
                  vsa + buf * VSZ + (uint32_t)((wn * 24) * 40) * 2 + kb + b_off);
            ldsm2(bf[2][0], bf[2][1],
                  vsa + buf * VSZ + (uint32_t)((wn * 24 + 16) * 40) * 2 + kb + b2_off);
#pragma unroll
            for (int nt = 0; nt < 3; nt++) mma16h(acc[nt], af, bf[nt]);
        }
        if (!more) break;
        CP_WAIT(0);
        __syncthreads();
        buf ^= 1;
    }

#pragma unroll
    for (int nt = 0; nt < 3; nt++)
#pragma unroll
        for (int half = 0; half < 2; half++) {
            const int q = qbase + wm * 16 + g + half * 8;
            const int d = wn * 24 + nt * 8 + 2 * t;
            *(__half2*)(g_O + (size_t)(bb * NSEQ + q) * DIM + h * HD + d) =
                __floats2half2_rn(acc[nt][half * 2], acc[nt][half * 2 + 1]);
        }
#undef PV_CP
}

// ---------------- launch ------------------------------------------------------
extern "C" void kernel_launch(void* const* d_in, const int* in_sizes, int n_in,
                              void* d_out, int out_size) {
    const float* x      = (const float*)d_in[0];
    const float* w_qkv  = (const float*)d_in[1];
    const float* b_qkv  = (const float*)d_in[2];
    const float* w_l    = (const float*)d_in[3];
    const float* b_l    = (const float*)d_in[4];
    const float* w_w    = (const float*)d_in[5];
    const float* b_w    = (const float*)d_in[6];
    const float* w_proj = (const float*)d_in[7];
    const float* b_proj = (const float*)d_in[8];
    float* out = (float*)d_out;

    const int mm_smem = 2 * ABUF + 2 * WBUF;   // 61440 B
    cudaFuncSetAttribute(mm_fp16<0>, cudaFuncAttributeMaxDynamicSharedMemorySize, mm_smem);
    cudaFuncSetAttribute(mm_fp16<1>, cudaFuncAttributeMaxDynamicSharedMemorySize, mm_smem);

    __half* xh;  cudaGetSymbolAddress((void**)&xh, g_xh);
    __half* wqh; cudaGetSymbolAddress((void**)&wqh, g_wqkvh);
    __half* wph; cudaGetSymbolAddress((void**)&wph, g_wprojh);
    __half* Oh;  cudaGetSymbolAddress((void**)&Oh, g_O);

    // K0: merged fp32 -> fp16 conversion
    f2h3_kernel<<<1036, 256>>>(x, xh, BATCH * NSEQ * DIM / 4,
                               w_qkv, wqh, 3 * DIM * DIM / 4,
                               w_proj, wph, DIM * DIM / 4);

    // K1: QKV projection  [M=8192, N=2304, K=768]
    mm_fp16<0><<<dim3(3 * DIM / 128, BATCH * NSEQ / 256), 512, mm_smem>>>(
        xh, wqh, b_qkv, nullptr, DIM, 3 * DIM);

    // Per-batch S-pipeline: one 32MB slice of g_S stays L2-resident across
    // qk(b) -> mix(b) -> pv(b), eliminating the DRAM round-trip.
    for (int b = 0; b < BATCH; b++) {
        qk_fp16<<<dim3(NSEQ / 256, NSEQ / 128, NH), 512>>>(b);
        mix_softmax_kernel<<<NSEQ, 256>>>(w_l, b_l, w_w, b_w, b);
        pv_fp16<<<dim3(NSEQ / 64, 1, NH), 256>>>(b);
    }

    // K5: output projection  [M=8192, N=768, K=768]
    mm_fp16<1><<<dim3(DIM / 128, BATCH * NSEQ / 256), 512, mm_smem>>>(
        Oh, wph, b_proj, out, DIM, DIM);
}

// round 17
// speedup vs baseline: 1.3348x; 1.3348x over previous
#include <cuda_runtime.h>
#include <cuda_fp16.h>
#include <cstdint>

#define BATCH 8
#define NSEQ 1024
#define DIM 768
#define NH 16
#define HD 48
#define SCALE 0.14433756729740643f  /* 48^-0.5 */
#define SPH 1032                     /* fp16 smem stride (halfs) for mix kernel */

// ---------------- scratch (static __device__, allocation-guard safe) ----------
__device__ __align__(256) __half g_xh[BATCH * NSEQ * DIM];
__device__ __align__(256) __half g_wqkvh[3 * DIM * DIM];
__device__ __align__(256) __half g_wprojh[DIM * DIM];
__device__ __align__(256) __half g_q[BATCH * NH * NSEQ * HD];       // [b][h][n][d] (pre-scaled)
__device__ __align__(256) __half g_k[BATCH * NH * NSEQ * HD];       // [b][h][n][d]
__device__ __align__(256) __half g_v[BATCH * NH * HD * NSEQ];       // [b][h][d][n]  TRANSPOSED
__device__ __align__(256) __half g_S[(size_t)BATCH * NH * NSEQ * NSEQ];
__device__ __align__(256) __half g_O[BATCH * NSEQ * DIM];           // attn out pre-proj (fp16)

// ---------------- helpers -----------------------------------------------------
__device__ __forceinline__ void mma16h(float* c, const uint32_t* a, const uint32_t* b) {
    asm volatile(
        "mma.sync.aligned.m16n8k16.row.col.f32.f16.f16.f32 "
        "{%0,%1,%2,%3},{%4,%5,%6,%7},{%8,%9},{%0,%1,%2,%3};"
        : "+f"(c[0]), "+f"(c[1]), "+f"(c[2]), "+f"(c[3])
        : "r"(a[0]), "r"(a[1]), "r"(a[2]), "r"(a[3]), "r"(b[0]), "r"(b[1]));
}
__device__ __forceinline__ void ldsm4(uint32_t& r0, uint32_t& r1, uint32_t& r2, uint32_t& r3,
                                      uint32_t addr) {
    asm volatile("ldmatrix.sync.aligned.m8n8.x4.shared.b16 {%0,%1,%2,%3}, [%4];"
        : "=r"(r0), "=r"(r1), "=r"(r2), "=r"(r3) : "r"(addr));
}
__device__ __forceinline__ void ldsm2(uint32_t& r0, uint32_t& r1, uint32_t addr) {
    asm volatile("ldmatrix.sync.aligned.m8n8.x2.shared.b16 {%0,%1}, [%2];"
        : "=r"(r0), "=r"(r1) : "r"(addr));
}
__device__ __forceinline__ void ldsm2t(uint32_t& r0, uint32_t& r1, uint32_t addr) {
    asm volatile("ldmatrix.sync.aligned.m8n8.x2.trans.shared.b16 {%0,%1}, [%2];"
        : "=r"(r0), "=r"(r1) : "r"(addr));
}
__device__ __forceinline__ uint32_t packh2(float x, float y) {
    __half2 h = __floats2half2_rn(x, y);
    return *(uint32_t*)&h;
}

#define CP16(dst_u32, src_ptr) \
    asm volatile("cp.async.cg.shared.global [%0], [%1], 16;" :: "r"(dst_u32), "l"(src_ptr))
#define CP_COMMIT()  asm volatile("cp.async.commit_group;" ::)
#define CP_WAIT(n)   asm volatile("cp.async.wait_group %0;" :: "n"(n))

// ---------------- K0: merged fp32 -> fp16 conversion (3 arrays, 1 launch) -----
__global__ __launch_bounds__(256) void f2h3_kernel(
    const float* __restrict__ a, __half* __restrict__ oa, int na4,
    const float* __restrict__ b, __half* __restrict__ ob, int nb4,
    const float* __restrict__ c, __half* __restrict__ oc, int nc4) {
    const int total = na4 + nb4 + nc4;
    for (int i = blockIdx.x * 256 + threadIdx.x; i < total; i += gridDim.x * 256) {
        const float* in;
        __half* out;
        int idx;
        if (i < na4)            { in = a; out = oa; idx = i; }
        else if (i < na4 + nb4) { in = b; out = ob; idx = i - na4; }
        else                    { in = c; out = oc; idx = i - na4 - nb4; }
        float4 v = ((const float4*)in)[idx];
        ((__half2*)out)[2 * idx]     = __floats2half2_rn(v.x, v.y);
        ((__half2*)out)[2 * idx + 1] = __floats2half2_rn(v.z, v.w);
    }
}

// ---------------- mm_fp16: qkv (MODE 0) & proj (MODE 1) -----------------------
// 512 threads, block tile 256(M) x 128(N), K-tile 32, 2-stage cp.async, fp32 acc.
#define ABUF (256 * 40 * 2)
#define WBUF (128 * 40 * 2)
template <int MODE>
__global__ __launch_bounds__(512) void mm_fp16(
    const __half* __restrict__ A, const __half* __restrict__ W,
    const float* __restrict__ bias, float* __restrict__ C, int K, int Nc) {
    extern __shared__ __half smem_mm[];

    const int tid = threadIdx.x;
    const int m0 = blockIdx.y * 256;
    const int n0 = blockIdx.x * 128;

    const int warp = tid >> 5, lane = tid & 31;
    const int wm = warp >> 2, wn = warp & 3;   // 4 x 4 warps
    const int g = lane >> 2, t = lane & 3;

    const uint32_t sa = (uint32_t)__cvta_generic_to_shared(smem_mm);
    const uint32_t sw = sa + 2 * ABUF;

    const uint32_t a_off = (uint32_t)((lane & 15) * 40 + (lane >> 4) * 8) * 2;
    const uint32_t b_off = (uint32_t)((((lane >> 4) << 3) + (lane & 7)) * 40 +
                                      (((lane >> 3) & 1) << 3)) * 2;

#define MM_CP(buf, kt)                                                         \
    do {                                                                       \
        _Pragma("unroll")                                                      \
        for (int j = 0; j < 2; j++) {         /* A: 256 rows x 4 chunks */     \
            const int i = tid + 512 * j;                                       \
            const int r = i >> 2, c = (i & 3) * 8;                             \
            CP16(sa + (buf) * ABUF + (uint32_t)(r * 40 + c) * 2,               \
                 A + (size_t)(m0 + r) * K + (kt) + c);                         \
        }                                                                      \
        {                                      /* W: 128 rows x 4 chunks */    \
            const int r = tid >> 2, c = (tid & 3) * 8;                         \
            CP16(sw + (buf) * WBUF + (uint32_t)(r * 40 + c) * 2,               \
                 W + (size_t)(n0 + r) * K + (kt) + c);                         \
        }                                                                      \
        CP_COMMIT();                                                           \
    } while (0)

    float acc[4][4][4];
#pragma unroll
    for (int i = 0; i < 4; i++)
#pragma unroll
        for (int j = 0; j < 4; j++)
#pragma unroll
            for (int e = 0; e < 4; e++) acc[i][j][e] = 0.f;

    MM_CP(0, 0);
    CP_WAIT(0);
    __syncthreads();

    int buf = 0;
    for (int kt = 32;; kt += 32) {
        const bool more = kt < K;
        if (more) MM_CP(buf ^ 1, kt);
#pragma unroll
        for (int ks = 0; ks < 2; ks++) {
            const uint32_t kb = (uint32_t)(ks * 16) * 2;
            uint32_t af[4][4], bf[4][2];
#pragma unroll
            for (int mt = 0; mt < 4; mt++)
                ldsm4(af[mt][0], af[mt][1], af[mt][2], af[mt][3],
                      sa + buf * ABUF + (uint32_t)((wm * 64 + mt * 16) * 40) * 2 + kb + a_off);
#pragma unroll
            for (int ntp = 0; ntp < 2; ntp++)
                ldsm4(bf[2 * ntp][0], bf[2 * ntp][1], bf[2 * ntp + 1][0], bf[2 * ntp + 1][1],
                      sw + buf * WBUF + (uint32_t)((wn * 32 + ntp * 16) * 40) * 2 + kb + b_off);
#pragma unroll
            for (int mt = 0; mt < 4; mt++)
#pragma unroll
                for (int nt = 0; nt < 4; nt++) mma16h(acc[mt][nt], af[mt], bf[nt]);
        }
        if (!more) break;
        CP_WAIT(0);
        __syncthreads();
        buf ^= 1;
    }

#pragma unroll
    for (int mt = 0; mt < 4; mt++) {
#pragma unroll
        for (int nt = 0; nt < 4; nt++) {
#pragma unroll
            for (int half = 0; half < 2; half++) {
                const int m = m0 + wm * 64 + mt * 16 + g + half * 8;
                const int c = n0 + wn * 32 + nt * 8 + 2 * t;   // always even
                const float v0 = acc[mt][nt][half * 2 + 0];
                const float v1 = acc[mt][nt][half * 2 + 1];
                if (MODE == 0) {
                    const float w0 = v0 + bias[c], w1 = v1 + bias[c + 1];
                    const int b = m >> 10, n = m & 1023;
                    const int ttt = c / DIM;
                    const int rr = c - ttt * DIM;
                    const int h = rr / HD, d = rr - h * HD;    // d even, d+1 same head
                    const int bh = b * NH + h;
                    if (ttt == 0)
                        *(__half2*)&g_q[((size_t)bh * NSEQ + n) * HD + d] =
                            __floats2half2_rn(w0 * SCALE, w1 * SCALE);
                    else if (ttt == 1)
                        *(__half2*)&g_k[((size_t)bh * NSEQ + n) * HD + d] =
                            __floats2half2_rn(w0, w1);
                    else {
                        g_v[((size_t)bh * HD + d) * NSEQ + n] = __float2half(w0);
                        g_v[((size_t)bh * HD + d + 1) * NSEQ + n] = __float2half(w1);
                    }
                } else {
                    float2 o = make_float2(v0 + bias[c], v1 + bias[c + 1]);
                    *(float2*)(C + (size_t)m * Nc + c) = o;
                }
            }
        }
    }
#undef MM_CP
}

// ---------------- K2: S = q @ k^T per (b,h), 512 thr, tile 128q x 256k --------
__global__ __launch_bounds__(512) void qk_fp16() {
    __shared__ __half Qs[128][56];
    __shared__ __half Ks[256][56];

    const int tid = threadIdx.x;
    const int bh = blockIdx.z;
    const int q0 = blockIdx.y * 128;
    const int k0 = blockIdx.x * 256;

    const __half* Qg = g_q + (size_t)bh * NSEQ * HD;
    const __half* Kg = g_k + (size_t)bh * NSEQ * HD;

    const uint32_t sq = (uint32_t)__cvta_generic_to_shared(&Qs[0][0]);
    const uint32_t sk = (uint32_t)__cvta_generic_to_shared(&Ks[0][0]);

#pragma unroll
    for (int j = 0; j < 2; j++) {
        const int i = tid + 512 * j;
        if (i < 768) {
            const int r = i / 6, c = (i % 6) * 8;
            CP16(sq + (uint32_t)(r * 56 + c) * 2, Qg + (size_t)(q0 + r) * HD + c);
        }
    }
#pragma unroll
    for (int j = 0; j < 3; j++) {
        const int i = tid + 512 * j;
        const int r = i / 6, c = (i % 6) * 8;
        CP16(sk + (uint32_t)(r * 56 + c) * 2, Kg + (size_t)(k0 + r) * HD + c);
    }
    CP_COMMIT();
    CP_WAIT(0);
    __syncthreads();

    const int warp = tid >> 5, lane = tid & 31;
    const int wm = warp >> 3, wn = warp & 7;   // 2 x 8 warps
    const int g = lane >> 2, t = lane & 3;

    const uint32_t a_off = (uint32_t)((lane & 15) * 56 + (lane >> 4) * 8) * 2;
    const uint32_t b_off = (uint32_t)((((lane >> 4) << 3) + (lane & 7)) * 56 +
                                      (((lane >> 3) & 1) << 3)) * 2;

    float acc[4][4][4];
#pragma unroll
    for (int i = 0; i < 4; i++)
#pragma unroll
        for (int j = 0; j < 4; j++)
#pragma unroll
            for (int e = 0; e < 4; e++) acc[i][j][e] = 0.f;

#pragma unroll
    for (int ks = 0; ks < 3; ks++) {
        const uint32_t kb = (uint32_t)(ks * 16) * 2;
        uint32_t af[4][4], bf[4][2];
#pragma unroll
        for (int mt = 0; mt < 4; mt++)
            ldsm4(af[mt][0], af[mt][1], af[mt][2], af[mt][3],
                  sq + (uint32_t)((wm * 64 + mt * 16) * 56) * 2 + kb + a_off);
#pragma unroll
        for (int ntp = 0; ntp < 2; ntp++)
            ldsm4(bf[2 * ntp][0], bf[2 * ntp][1], bf[2 * ntp + 1][0], bf[2 * ntp + 1][1],
                  sk + (uint32_t)((wn * 32 + ntp * 16) * 56) * 2 + kb + b_off);
#pragma unroll
        for (int mt = 0; mt < 4; mt++)
#pragma unroll
            for (int nt = 0; nt < 4; nt++) mma16h(acc[mt][nt], af[mt], bf[nt]);
    }

    __half* Sg = g_S + (size_t)bh * NSEQ * NSEQ;
#pragma unroll
    for (int mt = 0; mt < 4; mt++)
#pragma unroll
        for (int nt = 0; nt < 4; nt++)
#pragma unroll
            for (int half = 0; half < 2; half++) {
                const int m = q0 + wm * 64 + mt * 16 + g + half * 8;
                const int c = k0 + wn * 32 + nt * 8 + 2 * t;
                *(__half2*)(Sg + (size_t)m * NSEQ + c) =
                    __floats2half2_rn(acc[mt][nt][half * 2], acc[mt][nt][half * 2 + 1]);
            }
}

// ---------------- K3: mix1+exp fused -> inv-folded mix2 -----------------------
// exp applied to mix1's fp32 mma output in-register; per-head sums via quad
// shuffle + smem atomics. Softmax middle sweep eliminated entirely.
__global__ __launch_bounds__(256) void mix_softmax_kernel(
    const float* __restrict__ wl, const float* __restrict__ bl,
    const float* __restrict__ ww, const float* __restrict__ bw) {
    __shared__ __half s[NH][SPH];
    __shared__ float s_sum[NH];

    const int tid = threadIdx.x;
    const int lane = tid & 31, warp = tid >> 5;
    const int ar = lane >> 2;
    const int ac = lane & 3;
    const int bq = blockIdx.x;
    const int b = bq >> 10, q = bq & 1023;

    const uint32_t ss = (uint32_t)__cvta_generic_to_shared(&s[0][0]);

    uint32_t la[4];
    la[0] = packh2(wl[ar * NH + 2 * ac], wl[ar * NH + 2 * ac + 1]);
    la[1] = packh2(wl[(ar + 8) * NH + 2 * ac], wl[(ar + 8) * NH + 2 * ac + 1]);
    la[2] = packh2(wl[ar * NH + 2 * ac + 8], wl[ar * NH + 2 * ac + 9]);
    la[3] = packh2(wl[(ar + 8) * NH + 2 * ac + 8], wl[(ar + 8) * NH + 2 * ac + 9]);
    float wwv[8];
    wwv[0] = ww[ar * NH + 2 * ac];        wwv[1] = ww[ar * NH + 2 * ac + 1];
    wwv[2] = ww[(ar + 8) * NH + 2 * ac];  wwv[3] = ww[(ar + 8) * NH + 2 * ac + 1];
    wwv[4] = ww[ar * NH + 2 * ac + 8];    wwv[5] = ww[ar * NH + 2 * ac + 9];
    wwv[6] = ww[(ar + 8) * NH + 2 * ac + 8]; wwv[7] = ww[(ar + 8) * NH + 2 * ac + 9];
    const float bl0 = bl[ar], bl1 = bl[ar + 8];
    const float bw0 = bw[ar], bw1 = bw[ar + 8];

    const size_t rowbase = (size_t)(b * NH) * NSEQ * NSEQ + (size_t)q * NSEQ;

    if (tid < NH) s_sum[tid] = 0.f;
#pragma unroll
    for (int j = 0; j < 8; j++) {
        const int i = tid + 256 * j;
        const int h = i >> 7, c = (i & 127) * 8;
        CP16(ss + (uint32_t)(h * SPH + c) * 2,
             g_S + rowbase + (size_t)h * NSEQ * NSEQ + c);
    }
    CP_COMMIT();
    CP_WAIT(0);
    __syncthreads();

    const uint32_t bt_off = (uint32_t)((lane & 15) * SPH) * 2;

    // mix1 + exp fused (in place; warp owns cols [warp*128, +128))
    float sum0 = 0.f, sum1 = 0.f;
#pragma unroll 4
    for (int c0 = warp * 128; c0 < warp * 128 + 128; c0 += 8) {
        uint32_t bf[2];
        ldsm2t(bf[0], bf[1], ss + bt_off + (uint32_t)c0 * 2);
        float c[4] = {bl0, bl0, bl1, bl1};
        mma16h(c, la, bf);
        const float e0 = __expf(c[0]), e1 = __expf(c[1]);
        const float e2 = __expf(c[2]), e3 = __expf(c[3]);
        *(__half2*)&s[ar][c0 + 2 * ac] = __floats2half2_rn(e0, e1);
        *(__half2*)&s[ar + 8][c0 + 2 * ac] = __floats2half2_rn(e2, e3);
        sum0 += e0 + e1;
        sum1 += e2 + e3;
    }
    // reduce across the 4-lane quad sharing ar, then one atomic per (warp,row)
    sum0 += __shfl_xor_sync(0xffffffffu, sum0, 1);
    sum0 += __shfl_xor_sync(0xffffffffu, sum0, 2);
    sum1 += __shfl_xor_sync(0xffffffffu, sum1, 1);
    sum1 += __shfl_xor_sync(0xffffffffu, sum1, 2);
    if (ac == 0) {
        atomicAdd(&s_sum[ar], sum0);
        atomicAdd(&s_sum[ar + 8], sum1);
    }
    __syncthreads();

    // fold 1/Z into mix2 A fragments (columns of A = head index h)
    const float i0 = 1.f / s_sum[2 * ac], i1 = 1.f / s_sum[2 * ac + 1];
    const float i2 = 1.f / s_sum[2 * ac + 8], i3 = 1.f / s_sum[2 * ac + 9];
    uint32_t wa[4];
    wa[0] = packh2(wwv[0] * i0, wwv[1] * i1);
    wa[1] = packh2(wwv[2] * i0, wwv[3] * i1);
    wa[2] = packh2(wwv[4] * i2, wwv[5] * i3);
    wa[3] = packh2(wwv[6] * i2, wwv[7] * i3);

    // mix2 in place (reads unnormalized e; normalization carried by wa)
#pragma unroll 4
    for (int c0 = warp * 128; c0 < warp * 128 + 128; c0 += 8) {
        uint32_t bf[2];
        ldsm2t(bf[0], bf[1], ss + bt_off + (uint32_t)c0 * 2);
        float c[4] = {bw0, bw0, bw1, bw1};
        mma16h(c, wa, bf);
        *(__half2*)&s[ar][c0 + 2 * ac] = __floats2half2_rn(c[0], c[1]);
        *(__half2*)&s[ar + 8][c0 + 2 * ac] = __floats2half2_rn(c[2], c[3]);
    }
    __syncthreads();

    // coalesced store s -> g_S
#pragma unroll
    for (int j = 0; j < 8; j++) {
        const int i = tid + 256 * j;
        const int h = i >> 7, c = (i & 127) * 8;
        float4 v = *(const float4*)&s[h][c];
        *(float4*)(g_S + rowbase + (size_t)h * NSEQ * NSEQ + c) = v;
    }
}

// ---------------- K4: O = P @ V per (b,h), fp16 mma + ldmatrix + cp.async -----
__global__ __launch_bounds__(256) void pv_fp16() {
    __shared__ __half Ps[2][128][40];
    __shared__ __half Vs[2][HD][40];

    const int bh = blockIdx.z;
    const int tid = threadIdx.x;
    const int qbase = blockIdx.x * 128;
    const __half* Pg = g_S + (size_t)bh * NSEQ * NSEQ + (size_t)qbase * NSEQ;
    const __half* Vg = g_v + (size_t)bh * HD * NSEQ;   // [d][n]

    const int warp = tid >> 5, lane = tid & 31;
    const int wm = warp >> 1, wn = warp & 1;
    const int g = lane >> 2, t = lane & 3;

    const uint32_t psa = (uint32_t)__cvta_generic_to_shared(&Ps[0][0][0]);
    const uint32_t vsa = (uint32_t)__cvta_generic_to_shared(&Vs[0][0][0]);
    const uint32_t PSZ = 128 * 40 * 2;
    const uint32_t VSZ = HD * 40 * 2;

    const uint32_t a_off = (uint32_t)((lane & 15) * 40 + (lane >> 4) * 8) * 2;
    const uint32_t b_off = (uint32_t)((((lane >> 4) << 3) + (lane & 7)) * 40 +
                                      (((lane >> 3) & 1) << 3)) * 2;
    const uint32_t b2_off = (uint32_t)((lane & 7) * 40 + (((lane >> 3) & 1) << 3)) * 2;

#define PV_CP(buf, kt)                                                          \
    do {                                                                        \
        _Pragma("unroll")                                                       \
        for (int j = 0; j < 2; j++) {                                           \
            const int i = tid + 256 * j;                                        \
            const int r = i >> 2, c = (i & 3) * 8;                              \
            CP16(psa + (buf) * PSZ + (uint32_t)(r * 40 + c) * 2,                \
                 Pg + (size_t)r * NSEQ + (kt) + c);                             \
        }                                                                       \
        if (tid < 192) {                                                        \
            const int d = tid >> 2, c = (tid & 3) * 8;                          \
            CP16(vsa + (buf) * VSZ + (uint32_t)(d * 40 + c) * 2,                \
                 Vg + (size_t)d * NSEQ + (kt) + c);                             \
        }                                                                       \
        CP_COMMIT();                                                            \
    } while (0)

    float acc[2][3][4];
#pragma unroll
    for (int i = 0; i < 2; i++)
#pragma unroll
        for (int j = 0; j < 3; j++)
#pragma unroll
            for (int e = 0; e < 4; e++) acc[i][j][e] = 0.f;

    PV_CP(0, 0);
    CP_WAIT(0);
    __syncthreads();

    int buf = 0;
    for (int kt = 32;; kt += 32) {
        const bool more = kt < NSEQ;
        if (more) PV_CP(buf ^ 1, kt);
#pragma unroll
        for (int ks = 0; ks < 2; ks++) {
            const uint32_t kb = (uint32_t)(ks * 16) * 2;
            uint32_t af[2][4], bf[3][2];
#pragma unroll
            for (int mt = 0; mt < 2; mt++)
                ldsm4(af[mt][0], af[mt][1], af[mt][2], af[mt][3],
                      psa + buf * PSZ + (uint32_t)((wm * 32 + mt * 16) * 40) * 2 + kb + a_off);
            ldsm4(bf[0][0], bf[0][1], bf[1][0], bf[1][1],
                  vsa + buf * VSZ + (uint32_t)((wn * 24) * 40) * 2 + kb + b_off);
            ldsm2(bf[2][0], bf[2][1],
                  vsa + buf * VSZ + (uint32_t)((wn * 24 + 16) * 40) * 2 + kb + b2_off);
#pragma unroll
            for (int mt = 0; mt < 2; mt++)
#pragma unroll
                for (int nt = 0; nt < 3; nt++) mma16h(acc[mt][nt], af[mt], bf[nt]);
        }
        if (!more) break;
        CP_WAIT(0);
        __syncthreads();
        buf ^= 1;
    }

    const int b = bh >> 4, h = bh & 15;
#pragma unroll
    for (int mt = 0; mt < 2; mt++)
#pragma unroll
        for (int nt = 0; nt < 3; nt++)
#pragma unroll
            for (int half = 0; half < 2; half++) {
                const int q = qbase + wm * 32 + mt * 16 + g + half * 8;
                const int d = wn * 24 + nt * 8 + 2 * t;
                *(__half2*)(g_O + (size_t)(b * NSEQ + q) * DIM + h * HD + d) =
                    __floats2half2_rn(acc[mt][nt][half * 2], acc[mt][nt][half * 2 + 1]);
            }
#undef PV_CP
}

// ---------------- launch ------------------------------------------------------
extern "C" void kernel_launch(void* const* d_in, const int* in_sizes, int n_in,
                              void* d_out, int out_size) {
    const float* x      = (const float*)d_in[0];
    const float* w_qkv  = (const float*)d_in[1];
    const float* b_qkv  = (const float*)d_in[2];
    const float* w_l    = (const float*)d_in[3];
    const float* b_l    = (const float*)d_in[4];
    const float* w_w    = (const float*)d_in[5];
    const float* b_w    = (const float*)d_in[6];
    const float* w_proj = (const float*)d_in[7];
    const float* b_proj = (const float*)d_in[8];
    float* out = (float*)d_out;

    const int mm_smem = 2 * ABUF + 2 * WBUF;   // 61440 B
    cudaFuncSetAttribute(mm_fp16<0>, cudaFuncAttributeMaxDynamicSharedMemorySize, mm_smem);
    cudaFuncSetAttribute(mm_fp16<1>, cudaFuncAttributeMaxDynamicSharedMemorySize, mm_smem);

    __half* xh;  cudaGetSymbolAddress((void**)&xh, g_xh);
    __half* wqh; cudaGetSymbolAddress((void**)&wqh, g_wqkvh);
    __half* wph; cudaGetSymbolAddress((void**)&wph, g_wprojh);
    __half* Oh;  cudaGetSymbolAddress((void**)&Oh, g_O);

    // K0: merged fp32 -> fp16 conversion
    f2h3_kernel<<<1036, 256>>>(x, xh, BATCH * NSEQ * DIM / 4,
                               w_qkv, wqh, 3 * DIM * DIM / 4,
                               w_proj, wph, DIM * DIM / 4);

    // K1: QKV projection  [M=8192, N=2304, K=768]
    mm_fp16<0><<<dim3(3 * DIM / 128, BATCH * NSEQ / 256), 512, mm_smem>>>(
        xh, wqh, b_qkv, nullptr, DIM, 3 * DIM);
    // K2: logits S = q @ k^T per (b,h)  (tile 128x256)
    qk_fp16<<<dim3(NSEQ / 256, NSEQ / 128, BATCH * NH), 512>>>();
    // K3: fused mix1+exp -> inv-folded mix2
    mix_softmax_kernel<<<BATCH * NSEQ, 256>>>(w_l, b_l, w_w, b_w);
    // K4: P @ V -> g_O (fp32 acc)
    pv_fp16<<<dim3(NSEQ / 128, 1, BATCH * NH), 256>>>();
    // K5: output projection  [M=8192, N=768, K=768]
    mm_fp16<1><<<dim3(DIM / 128, BATCH * NSEQ / 256), 512, mm_smem>>>(
        Oh, wph, b_proj, out, DIM, DIM);
}